// round 15
// baseline (speedup 1.0000x reference)
#include <cuda_runtime.h>
#include <math.h>
#include <stdint.h>

#define NROWS 32768
#define DDIM  256
#define KCB   1024
#define MT    128
#define GRIDP 152          // persistent CTAs (GB300: 152 SMs)
#define NUNITS 2048        // 256 rowblocks x 8 colblocks (128x128xK units)
#define ENTB  4096         // entropy blocks (8 rows each)
#define OUTB  2048         // output blocks (16 rows each)

// scratch (static device arrays: allowed)
__device__ float              g_dist[(size_t)NROWS * KCB];   // 134 MB
__device__ unsigned long long g_key[NROWS];                  // (dist_bits<<32)|col
__device__ float              g_b2[KCB];
__device__ float              g_avgp[KCB];
__device__ double             g_sample;
__device__ double             g_msum;
__device__ unsigned int       g_done;

// ---------------------------------------------------------------- K0: init
__global__ void k0_init(const float* __restrict__ cb) {
    int t = blockIdx.x * blockDim.x + threadIdx.x;   // grid covers 32768
    if (t < KCB) {
        const float4* r = (const float4*)(cb + (size_t)t * DDIM);
        double acc = 0.0;
        for (int i = 0; i < DDIM / 4; i++) {
            float4 v = r[i];
            acc += (double)v.x * v.x + (double)v.y * v.y
                 + (double)v.z * v.z + (double)v.w * v.w;
        }
        g_b2[t]   = (float)acc;
        g_avgp[t] = 0.0f;
    }
    if (t < NROWS) g_key[t] = 0xFFFFFFFFFFFFFFFFull;
    if (t == 0) { g_sample = 0.0; g_msum = 0.0; g_done = 0u; }
}

// --------------- K1: persistent fp32 SIMT GEMM, 8x8 thread tiles (R8/R13-proven)
// dist rounding = reference: fl(a2+b2) - fl(2*dot), dot fmaf d=0..255 in order.
#define ASTR 132
#define BSTR 132
#define BBUF (16 * BSTR)

__global__ __launch_bounds__(256, 1)
void k1_main(const float* __restrict__ x, const float* __restrict__ cb) {
    extern __shared__ float sm[];              // As[256][132] then Bs[2][16][132]
    __shared__ float a2s[MT];
    __shared__ float b2s[KCB];

    float* As = sm;
    float* Bs = sm + 256 * ASTR;

    const int tid = threadIdx.x;
    const int l   = tid & 31;
    const int tx  = tid & 15;
    const int ty  = tid >> 4;

    for (int i = tid; i < KCB; i += 256) b2s[i] = g_b2[i];

    const int u0 = (int)(((long long)blockIdx.x * NUNITS) / GRIDP);
    const int u1 = (int)(((long long)(blockIdx.x + 1) * NUNITS) / GRIDP);
    int cur_rb = -1;

    const int bcol = tid >> 1;
    const int bdh  = (tid & 1) * 8;

    for (int u = u0; u < u1; u++) {
        const int rb   = u >> 3;
        const int cbk  = u & 7;
        const int row0 = rb * MT;
        const int c0   = cbk * 128;

        if (rb != cur_rb) {
            __syncthreads();                   // prior unit's As readers done
            int arow = tid >> 1, db = (tid & 1) * 128;
            const float4* src = (const float4*)(x + (size_t)(row0 + arow) * DDIM + db);
            #pragma unroll
            for (int q = 0; q < 32; q++) {
                float4 v = src[q];
                int d = db + 4 * q;
                As[(d + 0) * ASTR + arow] = v.x;
                As[(d + 1) * ASTR + arow] = v.y;
                As[(d + 2) * ASTR + arow] = v.z;
                As[(d + 3) * ASTR + arow] = v.w;
            }
            if (tid < MT) {
                const float4* r = (const float4*)(x + (size_t)(row0 + tid) * DDIM);
                double acc = 0.0;
                #pragma unroll 4
                for (int i = 0; i < DDIM / 4; i++) {
                    float4 v = r[i];
                    acc += (double)v.x * v.x + (double)v.y * v.y
                         + (double)v.z * v.z + (double)v.w * v.w;
                }
                a2s[tid] = (float)acc;         // visible after phase-0 sync
            }
            cur_rb = rb;
        }

        float4 rbv0, rbv1;
        auto load_rb = [&](int kc) {
            const float4* src = (const float4*)(cb + (size_t)(c0 + bcol) * DDIM + kc * 16 + bdh);
            rbv0 = src[0]; rbv1 = src[1];
        };
        auto sts_rb = [&](int kc) {
            float* dst = Bs + (kc & 1) * BBUF + bdh * BSTR + bcol;
            dst[0 * BSTR] = rbv0.x; dst[1 * BSTR] = rbv0.y;
            dst[2 * BSTR] = rbv0.z; dst[3 * BSTR] = rbv0.w;
            dst[4 * BSTR] = rbv1.x; dst[5 * BSTR] = rbv1.y;
            dst[6 * BSTR] = rbv1.z; dst[7 * BSTR] = rbv1.w;
        };
        load_rb(0);
        sts_rb(0);

        float a2r[8];
        float acc[8][8];
        #pragma unroll
        for (int i = 0; i < 8; i++)
            #pragma unroll
            for (int j = 0; j < 8; j++) acc[i][j] = 0.0f;

        for (int kc = 0; kc < 16; kc++) {
            if (kc + 1 < 16) load_rb(kc + 1);
            __syncthreads();
            if (kc == 0) {
                #pragma unroll
                for (int i = 0; i < 8; i++) a2r[i] = a2s[ty * 8 + i];
            }
            const float* bbase = Bs + (kc & 1) * BBUF;
            #pragma unroll
            for (int dd = 0; dd < 16; dd++) {
                const float* arow = As + (kc * 16 + dd) * ASTR + ty * 8;
                const float* brow = bbase + dd * BSTR + tx * 8;
                float4 av0 = *(const float4*)(arow);
                float4 av1 = *(const float4*)(arow + 4);
                float4 bv0 = *(const float4*)(brow);
                float4 bv1 = *(const float4*)(brow + 4);
                float a[8] = {av0.x, av0.y, av0.z, av0.w, av1.x, av1.y, av1.z, av1.w};
                float b[8] = {bv0.x, bv0.y, bv0.z, bv0.w, bv1.x, bv1.y, bv1.z, bv1.w};
                #pragma unroll
                for (int i = 0; i < 8; i++)
                    #pragma unroll
                    for (int j = 0; j < 8; j++)
                        acc[i][j] = fmaf(a[i], b[j], acc[i][j]);
            }
            if (kc + 1 < 16) sts_rb(kc + 1);
        }

        // unit epilogue (R8 form): dist, scratch store, lex argmin merge
        const int cc0 = c0 + tx * 8;
        #pragma unroll
        for (int i = 0; i < 8; i++) {
            int R = ty * 8 + i;
            float a2 = a2r[i];
            float bd = 3.402823466e38f; int bc = 0;
            float dv[8];
            #pragma unroll
            for (int j = 0; j < 8; j++) {
                float t = a2 + b2s[cc0 + j];     // fl(a2 + b2)
                float d = t - 2.0f * acc[i][j];  // fl(t - 2ab)
                dv[j] = d;
                if (d < bd) { bd = d; bc = cc0 + j; }   // cols ascend: first-index ties
            }
            float4* dst = (float4*)(g_dist + (size_t)(row0 + R) * KCB + cc0);
            dst[0] = make_float4(dv[0], dv[1], dv[2], dv[3]);
            dst[1] = make_float4(dv[4], dv[5], dv[6], dv[7]);
            #pragma unroll
            for (int off = 8; off >= 1; off >>= 1) {    // lex (d, col) over 16 tx lanes
                float od = __shfl_xor_sync(0xffffffffu, bd, off);
                int   oc = __shfl_xor_sync(0xffffffffu, bc, off);
                if (od < bd || (od == bd && oc < bc)) { bd = od; bc = oc; }
            }
            if ((l & 15) == 0) {
                unsigned long long key =
                    ((unsigned long long)__float_as_uint(bd) << 32) | (unsigned)bc;
                atomicMin(&g_key[row0 + R], key);       // dists > 0: bit-order = value-order
            }
        }
    }
}

// ---- K2 (combined): blocks [0,ENTB) entropy; [ENTB,+OUTB) outputs;
//      last-to-finish block computes the final loss (folded K3).
__global__ __launch_bounds__(256)
void k2_combined(const float* __restrict__ x, const float* __restrict__ cb,
                 float* __restrict__ out, int write_aux, int write_loss) {
    __shared__ double sred[8];
    __shared__ int    is_last;
    const int tid  = threadIdx.x;
    const int lane = tid & 31;

    if (blockIdx.x < ENTB) {
        // ---------------- entropy: warp/row filtered softmax (proven R2/7/8/13) --
        int row = (blockIdx.x * 256 + tid) >> 5;
        const float4* dr = (const float4*)(g_dist + (size_t)row * KCB);

        float dmin = __uint_as_float((unsigned)(g_key[row] >> 32));
        float thr  = dmin + 0.90f;
        float M    = (-dmin) / 0.01f;

        float4 v[8];
        #pragma unroll
        for (int i = 0; i < 8; i++) v[i] = dr[i * 32 + lane];

        float S = 0.0f;
        #pragma unroll
        for (int i = 0; i < 8; i++) {
            if (v[i].x <= thr) S += expf((-v[i].x) / 0.01f - M);
            if (v[i].y <= thr) S += expf((-v[i].y) / 0.01f - M);
            if (v[i].z <= thr) S += expf((-v[i].z) / 0.01f - M);
            if (v[i].w <= thr) S += expf((-v[i].w) / 0.01f - M);
        }
        #pragma unroll
        for (int off = 16; off >= 1; off >>= 1)
            S += __shfl_xor_sync(0xffffffffu, S, off);

        float logS = logf(S);
        float accent = 0.0f;
        #pragma unroll
        for (int i = 0; i < 8; i++) {
            #pragma unroll
            for (int c = 0; c < 4; c++) {
                float d = (c == 0) ? v[i].x : (c == 1) ? v[i].y : (c == 2) ? v[i].z : v[i].w;
                if (d <= thr) {
                    float sh = (-d) / 0.01f - M;
                    float p  = expf(sh) / S;
                    accent += p * (sh - logS);   // +1e-5 on logits is an fp32 no-op here
                    atomicAdd(&g_avgp[i * 128 + lane * 4 + c], p);
                }
            }
        }
        #pragma unroll
        for (int off = 16; off >= 1; off >>= 1)
            accent += __shfl_xor_sync(0xffffffffu, accent, off);
        if (lane == 0) atomicAdd(&g_sample, (double)accent);
    } else {
        // ---------------- outputs: 16 rows/CTA, 16 threads/row, MLP-heavy ------
        const int base   = (blockIdx.x - ENTB) * 16;
        const int r16    = tid >> 4;            // row within CTA
        const int lane16 = tid & 15;
        const int row    = base + r16;

        const int idx = (int)(g_key[row] & 0xFFFFFFFFull);   // broadcast load

        const float4* xr   = (const float4*)(x  + (size_t)row * DDIM);
        const float4* cr   = (const float4*)(cb + (size_t)idx * DDIM);
        float4*       orow = (float4*)(out + (size_t)row * DDIM);

        float4 xv[4], cv[4];
        #pragma unroll
        for (int q = 0; q < 4; q++) {           // 8 independent loads in flight
            int e = q * 16 + lane16;
            xv[q] = xr[e];
            cv[q] = cr[e];
        }
        double lsq = 0.0;
        #pragma unroll
        for (int q = 0; q < 4; q++) {
            int e = q * 16 + lane16;
            float dx = cv[q].x - xv[q].x, dy = cv[q].y - xv[q].y;
            float dz = cv[q].z - xv[q].z, dw = cv[q].w - xv[q].w;
            orow[e] = make_float4(xv[q].x + dx, xv[q].y + dy,
                                  xv[q].z + dz, xv[q].w + dw);
            lsq += (double)dx * dx + (double)dy * dy
                 + (double)dz * dz + (double)dw * dw;
        }
        if (write_aux && lane16 == 0)
            out[(size_t)NROWS * DDIM + 1 + row] = (float)idx;

        #pragma unroll
        for (int off = 16; off >= 1; off >>= 1)
            lsq += __shfl_xor_sync(0xffffffffu, lsq, off);
        if (lane == 0) sred[tid >> 5] = lsq;
        __syncthreads();
        if (tid == 0) {
            double s = 0.0;
            for (int i = 0; i < 8; i++) s += sred[i];
            atomicAdd(&g_msum, s);
        }
    }

    // ---- folded K3: the last block to finish computes the final loss ----
    __threadfence();
    if (tid == 0)
        is_last = (atomicInc(&g_done, ENTB + OUTB - 1) == ENTB + OUTB - 1);
    __syncthreads();
    if (is_last) {
        __shared__ float w3[8];
        float term = 0.0f;
        #pragma unroll
        for (int q = 0; q < 4; q++) {            // 256 threads x 4 cols = 1024
            float ap = g_avgp[tid + q * 256] / 32768.0f;
            term += ap * logf(ap + 1e-5f);
        }
        #pragma unroll
        for (int off = 16; off >= 1; off >>= 1)
            term += __shfl_xor_sync(0xffffffffu, term, off);
        if (lane == 0) w3[tid >> 5] = term;
        __syncthreads();
        if (tid == 0 && write_loss) {
            float tot = 0.0f;
            for (int i = 0; i < 8; i++) tot += w3[i];
            float avg_ent = -tot;
            float samp    = -(float)(g_sample / 32768.0);
            float entropy = samp - avg_ent;
            float m       = (float)(g_msum / 8388608.0);
            float loss    = (m * 0.25f + m) + entropy * 0.1f;
            out[(size_t)NROWS * DDIM] = loss;
        }
    }
}

// ---------------------------------------------------------------- launch
extern "C" void kernel_launch(void* const* d_in, const int* in_sizes, int n_in,
                              void* d_out, int out_size) {
    const float* x  = (const float*)d_in[0];
    const float* cb = (const float*)d_in[1];
    if (n_in >= 2 && in_sizes[0] == KCB * DDIM && in_sizes[1] == NROWS * DDIM) {
        const float* tmp = x; x = cb; cb = tmp;   // defensive: (codebook, x) order
    }
    float* out = (float*)d_out;
    int aux   = (out_size >= NROWS * DDIM + 1 + NROWS) ? 1 : 0;
    int wloss = (out_size > NROWS * DDIM) ? 1 : 0;

    static int init_done = 0;
    const int k1_smem = (256 * ASTR + 2 * 16 * BSTR) * 4;   // 152064 bytes
    if (!init_done) {
        cudaFuncSetAttribute(k1_main, cudaFuncAttributeMaxDynamicSharedMemorySize, k1_smem);
        init_done = 1;
    }

    k0_init<<<NROWS / 256, 256>>>(cb);
    k1_main<<<GRIDP, 256, k1_smem>>>(x, cb);
    k2_combined<<<ENTB + OUTB, 256>>>(x, cb, out, aux, wloss);
}

// round 16
// speedup vs baseline: 1.1077x; 1.1077x over previous
#include <cuda_runtime.h>
#include <math.h>
#include <stdint.h>

#define NROWS 32768
#define DDIM  256
#define KCB   1024
#define MT    128
#define GRIDP 152          // persistent CTAs (GB300: 152 SMs)
#define NUNITS 2048        // 256 rowblocks x 8 colblocks (128x128xK units)
#define ENTB  4096         // entropy blocks (8 rows each)
#define OUTB  2048         // output blocks (16 rows each)

// scratch (static device arrays: allowed)
__device__ float              g_dist[(size_t)NROWS * KCB];   // 134 MB
__device__ unsigned long long g_key[NROWS];                  // (dist_bits<<32)|col
__device__ float              g_b2[KCB];
__device__ float              g_avgp[KCB];
__device__ double             g_sample;
__device__ double             g_msum;

// ------------------- K0: warp-per-codebook-row b2 + init (latency-parallel)
__global__ void k0_init(const float* __restrict__ cb) {
    int t    = blockIdx.x * blockDim.x + threadIdx.x;   // 32768 threads
    int w    = t >> 5;                                  // 1024 warps = codebook rows
    int lane = t & 31;

    // b2[w]: each lane takes 8 consecutive elements; double FMA chain + shuffle reduce
    const float4* r = (const float4*)(cb + (size_t)w * DDIM);
    float4 v0 = r[lane * 2];
    float4 v1 = r[lane * 2 + 1];
    double acc = 0.0;
    acc += (double)v0.x * v0.x; acc += (double)v0.y * v0.y;
    acc += (double)v0.z * v0.z; acc += (double)v0.w * v0.w;
    acc += (double)v1.x * v1.x; acc += (double)v1.y * v1.y;
    acc += (double)v1.z * v1.z; acc += (double)v1.w * v1.w;
    #pragma unroll
    for (int off = 16; off >= 1; off >>= 1)
        acc += __shfl_xor_sync(0xffffffffu, acc, off);
    if (lane == 0) g_b2[w] = (float)acc;

    if (t < KCB) g_avgp[t] = 0.0f;
    g_key[t] = 0xFFFFFFFFFFFFFFFFull;
    if (t == 0) { g_sample = 0.0; g_msum = 0.0; }
}

// --------------- K1: persistent fp32 SIMT GEMM, 8x8 thread tiles (R8/R13-proven)
// dist rounding = reference: fl(a2+b2) - fl(2*dot), dot fmaf d=0..255 in order.
#define ASTR 132
#define BSTR 132
#define BBUF (16 * BSTR)

__global__ __launch_bounds__(256, 1)
void k1_main(const float* __restrict__ x, const float* __restrict__ cb) {
    extern __shared__ float sm[];              // As[256][132] then Bs[2][16][132]
    __shared__ float a2s[MT];
    __shared__ float b2s[KCB];

    float* As = sm;
    float* Bs = sm + 256 * ASTR;

    const int tid = threadIdx.x;
    const int l   = tid & 31;
    const int tx  = tid & 15;
    const int ty  = tid >> 4;

    for (int i = tid; i < KCB; i += 256) b2s[i] = g_b2[i];

    const int u0 = (int)(((long long)blockIdx.x * NUNITS) / GRIDP);
    const int u1 = (int)(((long long)(blockIdx.x + 1) * NUNITS) / GRIDP);
    int cur_rb = -1;

    const int bcol = tid >> 1;
    const int bdh  = (tid & 1) * 8;

    for (int u = u0; u < u1; u++) {
        const int rb   = u >> 3;
        const int cbk  = u & 7;
        const int row0 = rb * MT;
        const int c0   = cbk * 128;

        if (rb != cur_rb) {
            __syncthreads();                   // prior unit's As readers done
            int arow = tid >> 1, db = (tid & 1) * 128;
            const float4* src = (const float4*)(x + (size_t)(row0 + arow) * DDIM + db);
            #pragma unroll
            for (int q = 0; q < 32; q++) {
                float4 v = src[q];
                int d = db + 4 * q;
                As[(d + 0) * ASTR + arow] = v.x;
                As[(d + 1) * ASTR + arow] = v.y;
                As[(d + 2) * ASTR + arow] = v.z;
                As[(d + 3) * ASTR + arow] = v.w;
            }
            if (tid < MT) {
                const float4* r = (const float4*)(x + (size_t)(row0 + tid) * DDIM);
                double acc = 0.0;
                #pragma unroll 4
                for (int i = 0; i < DDIM / 4; i++) {
                    float4 v = r[i];
                    acc += (double)v.x * v.x + (double)v.y * v.y
                         + (double)v.z * v.z + (double)v.w * v.w;
                }
                a2s[tid] = (float)acc;         // visible after phase-0 sync
            }
            cur_rb = rb;
        }

        float4 rbv0, rbv1;
        auto load_rb = [&](int kc) {
            const float4* src = (const float4*)(cb + (size_t)(c0 + bcol) * DDIM + kc * 16 + bdh);
            rbv0 = src[0]; rbv1 = src[1];
        };
        auto sts_rb = [&](int kc) {
            float* dst = Bs + (kc & 1) * BBUF + bdh * BSTR + bcol;
            dst[0 * BSTR] = rbv0.x; dst[1 * BSTR] = rbv0.y;
            dst[2 * BSTR] = rbv0.z; dst[3 * BSTR] = rbv0.w;
            dst[4 * BSTR] = rbv1.x; dst[5 * BSTR] = rbv1.y;
            dst[6 * BSTR] = rbv1.z; dst[7 * BSTR] = rbv1.w;
        };
        load_rb(0);
        sts_rb(0);

        float a2r[8];
        float acc[8][8];
        #pragma unroll
        for (int i = 0; i < 8; i++)
            #pragma unroll
            for (int j = 0; j < 8; j++) acc[i][j] = 0.0f;

        for (int kc = 0; kc < 16; kc++) {
            if (kc + 1 < 16) load_rb(kc + 1);
            __syncthreads();
            if (kc == 0) {
                #pragma unroll
                for (int i = 0; i < 8; i++) a2r[i] = a2s[ty * 8 + i];
            }
            const float* bbase = Bs + (kc & 1) * BBUF;
            #pragma unroll
            for (int dd = 0; dd < 16; dd++) {
                const float* arow = As + (kc * 16 + dd) * ASTR + ty * 8;
                const float* brow = bbase + dd * BSTR + tx * 8;
                float4 av0 = *(const float4*)(arow);
                float4 av1 = *(const float4*)(arow + 4);
                float4 bv0 = *(const float4*)(brow);
                float4 bv1 = *(const float4*)(brow + 4);
                float a[8] = {av0.x, av0.y, av0.z, av0.w, av1.x, av1.y, av1.z, av1.w};
                float b[8] = {bv0.x, bv0.y, bv0.z, bv0.w, bv1.x, bv1.y, bv1.z, bv1.w};
                #pragma unroll
                for (int i = 0; i < 8; i++)
                    #pragma unroll
                    for (int j = 0; j < 8; j++)
                        acc[i][j] = fmaf(a[i], b[j], acc[i][j]);
            }
            if (kc + 1 < 16) sts_rb(kc + 1);
        }

        // unit epilogue (R8 form): dist, scratch store, lex argmin merge
        const int cc0 = c0 + tx * 8;
        #pragma unroll
        for (int i = 0; i < 8; i++) {
            int R = ty * 8 + i;
            float a2 = a2r[i];
            float bd = 3.402823466e38f; int bc = 0;
            float dv[8];
            #pragma unroll
            for (int j = 0; j < 8; j++) {
                float t = a2 + b2s[cc0 + j];     // fl(a2 + b2)
                float d = t - 2.0f * acc[i][j];  // fl(t - 2ab)
                dv[j] = d;
                if (d < bd) { bd = d; bc = cc0 + j; }   // cols ascend: first-index ties
            }
            float4* dst = (float4*)(g_dist + (size_t)(row0 + R) * KCB + cc0);
            dst[0] = make_float4(dv[0], dv[1], dv[2], dv[3]);
            dst[1] = make_float4(dv[4], dv[5], dv[6], dv[7]);
            #pragma unroll
            for (int off = 8; off >= 1; off >>= 1) {    // lex (d, col) over 16 tx lanes
                float od = __shfl_xor_sync(0xffffffffu, bd, off);
                int   oc = __shfl_xor_sync(0xffffffffu, bc, off);
                if (od < bd || (od == bd && oc < bc)) { bd = od; bc = oc; }
            }
            if ((l & 15) == 0) {
                unsigned long long key =
                    ((unsigned long long)__float_as_uint(bd) << 32) | (unsigned)bc;
                atomicMin(&g_key[row0 + R], key);       // dists > 0: bit-order = value-order
            }
        }
    }
}

// ---- K2 (combined, R13-proven): blocks [0,ENTB) entropy; [ENTB,+OUTB) outputs
__global__ __launch_bounds__(256)
void k2_combined(const float* __restrict__ x, const float* __restrict__ cb,
                 float* __restrict__ out, int write_aux) {
    const int tid  = threadIdx.x;
    const int lane = tid & 31;

    if (blockIdx.x < ENTB) {
        // ---------------- entropy: warp/row filtered softmax (proven R2/7/8/13) --
        int row = (blockIdx.x * 256 + tid) >> 5;
        const float4* dr = (const float4*)(g_dist + (size_t)row * KCB);

        float dmin = __uint_as_float((unsigned)(g_key[row] >> 32));
        float thr  = dmin + 0.90f;
        float M    = (-dmin) / 0.01f;

        float4 v[8];
        #pragma unroll
        for (int i = 0; i < 8; i++) v[i] = dr[i * 32 + lane];

        float S = 0.0f;
        #pragma unroll
        for (int i = 0; i < 8; i++) {
            if (v[i].x <= thr) S += expf((-v[i].x) / 0.01f - M);
            if (v[i].y <= thr) S += expf((-v[i].y) / 0.01f - M);
            if (v[i].z <= thr) S += expf((-v[i].z) / 0.01f - M);
            if (v[i].w <= thr) S += expf((-v[i].w) / 0.01f - M);
        }
        #pragma unroll
        for (int off = 16; off >= 1; off >>= 1)
            S += __shfl_xor_sync(0xffffffffu, S, off);

        float logS = logf(S);
        float accent = 0.0f;
        #pragma unroll
        for (int i = 0; i < 8; i++) {
            #pragma unroll
            for (int c = 0; c < 4; c++) {
                float d = (c == 0) ? v[i].x : (c == 1) ? v[i].y : (c == 2) ? v[i].z : v[i].w;
                if (d <= thr) {
                    float sh = (-d) / 0.01f - M;
                    float p  = expf(sh) / S;
                    accent += p * (sh - logS);   // +1e-5 on logits is an fp32 no-op here
                    atomicAdd(&g_avgp[i * 128 + lane * 4 + c], p);
                }
            }
        }
        #pragma unroll
        for (int off = 16; off >= 1; off >>= 1)
            accent += __shfl_xor_sync(0xffffffffu, accent, off);
        if (lane == 0) atomicAdd(&g_sample, (double)accent);
    } else {
        // ---------------- outputs: 16 rows/CTA, 16 threads/row, MLP-heavy ------
        __shared__ double sred[8];
        const int base   = (blockIdx.x - ENTB) * 16;
        const int r16    = tid >> 4;            // row within CTA
        const int lane16 = tid & 15;
        const int row    = base + r16;

        const int idx = (int)(g_key[row] & 0xFFFFFFFFull);   // broadcast load

        const float4* xr   = (const float4*)(x  + (size_t)row * DDIM);
        const float4* cr   = (const float4*)(cb + (size_t)idx * DDIM);
        float4*       orow = (float4*)(out + (size_t)row * DDIM);

        float4 xv[4], cv[4];
        #pragma unroll
        for (int q = 0; q < 4; q++) {           // 8 independent loads in flight
            int e = q * 16 + lane16;
            xv[q] = xr[e];
            cv[q] = cr[e];
        }
        double lsq = 0.0;
        #pragma unroll
        for (int q = 0; q < 4; q++) {
            int e = q * 16 + lane16;
            float dx = cv[q].x - xv[q].x, dy = cv[q].y - xv[q].y;
            float dz = cv[q].z - xv[q].z, dw = cv[q].w - xv[q].w;
            orow[e] = make_float4(xv[q].x + dx, xv[q].y + dy,
                                  xv[q].z + dz, xv[q].w + dw);
            lsq += (double)dx * dx + (double)dy * dy
                 + (double)dz * dz + (double)dw * dw;
        }
        if (write_aux && lane16 == 0)
            out[(size_t)NROWS * DDIM + 1 + row] = (float)idx;

        #pragma unroll
        for (int off = 16; off >= 1; off >>= 1)
            lsq += __shfl_xor_sync(0xffffffffu, lsq, off);
        if (lane == 0) sred[tid >> 5] = lsq;
        __syncthreads();
        if (tid == 0) {
            double s = 0.0;
            for (int i = 0; i < 8; i++) s += sred[i];
            atomicAdd(&g_msum, s);
        }
    }
}

// ---------------------------------------------------------------- K3: final loss
__global__ void k3_final(float* out, int write_loss) {
    __shared__ float w[32];
    int t = threadIdx.x;   // 1024 threads
    float ap   = g_avgp[t] / 32768.0f;
    float term = ap * logf(ap + 1e-5f);
    #pragma unroll
    for (int off = 16; off >= 1; off >>= 1)
        term += __shfl_xor_sync(0xffffffffu, term, off);
    if ((t & 31) == 0) w[t >> 5] = term;
    __syncthreads();
    if (t == 0) {
        float tot = 0.0f;
        for (int i = 0; i < 32; i++) tot += w[i];
        float avg_ent = -tot;
        float samp    = -(float)(g_sample / 32768.0);
        float entropy = samp - avg_ent;
        float m       = (float)(g_msum / 8388608.0);
        float loss    = (m * 0.25f + m) + entropy * 0.1f;
        if (write_loss) out[(size_t)NROWS * DDIM] = loss;
    }
}

// ---------------------------------------------------------------- launch
extern "C" void kernel_launch(void* const* d_in, const int* in_sizes, int n_in,
                              void* d_out, int out_size) {
    const float* x  = (const float*)d_in[0];
    const float* cb = (const float*)d_in[1];
    if (n_in >= 2 && in_sizes[0] == KCB * DDIM && in_sizes[1] == NROWS * DDIM) {
        const float* tmp = x; x = cb; cb = tmp;   // defensive: (codebook, x) order
    }
    float* out = (float*)d_out;
    int aux = (out_size >= NROWS * DDIM + 1 + NROWS) ? 1 : 0;

    static int init_done = 0;
    const int k1_smem = (256 * ASTR + 2 * 16 * BSTR) * 4;   // 152064 bytes
    if (!init_done) {
        cudaFuncSetAttribute(k1_main, cudaFuncAttributeMaxDynamicSharedMemorySize, k1_smem);
        init_done = 1;
    }

    k0_init<<<NROWS / 256, 256>>>(cb);
    k1_main<<<GRIDP, 256, k1_smem>>>(x, cb);
    k2_combined<<<ENTB + OUTB, 256>>>(x, cb, out, aux);
    k3_final<<<1, 1024>>>(out, (out_size > NROWS * DDIM) ? 1 : 0);
}

// round 17
// speedup vs baseline: 1.1194x; 1.0106x over previous
#include <cuda_runtime.h>
#include <math.h>
#include <stdint.h>

#define NROWS 32768
#define DDIM  256
#define KCB   1024
#define MT    128
#define GRIDP 152          // persistent CTAs (GB300: 152 SMs)
#define NUNITS 2048        // 256 rowblocks x 8 colblocks (128x128xK units)
#define ENTB  4096         // entropy blocks (8 rows each)
#define OUTB  2048         // output blocks (16 rows each)
#define NBANK 64           // atomic banks for g_sample / g_msum

// scratch (static device arrays: allowed)
__device__ float              g_dist[(size_t)NROWS * KCB];   // 134 MB
__device__ unsigned long long g_key[NROWS];                  // (dist_bits<<32)|col
__device__ float              g_b2[KCB];
__device__ float              g_avgp[KCB];
__device__ double             g_sampleb[NBANK];
__device__ double             g_msumb[NBANK];

// ------------------- K0: warp-per-codebook-row b2 + init (latency-parallel)
__global__ void k0_init(const float* __restrict__ cb) {
    int t    = blockIdx.x * blockDim.x + threadIdx.x;   // 32768 threads
    int w    = t >> 5;                                  // 1024 warps = codebook rows
    int lane = t & 31;

    const float4* r = (const float4*)(cb + (size_t)w * DDIM);
    float4 v0 = r[lane * 2];
    float4 v1 = r[lane * 2 + 1];
    double acc = 0.0;
    acc += (double)v0.x * v0.x; acc += (double)v0.y * v0.y;
    acc += (double)v0.z * v0.z; acc += (double)v0.w * v0.w;
    acc += (double)v1.x * v1.x; acc += (double)v1.y * v1.y;
    acc += (double)v1.z * v1.z; acc += (double)v1.w * v1.w;
    #pragma unroll
    for (int off = 16; off >= 1; off >>= 1)
        acc += __shfl_xor_sync(0xffffffffu, acc, off);
    if (lane == 0) g_b2[w] = (float)acc;

    if (t < KCB) g_avgp[t] = 0.0f;
    if (t < NBANK) { g_sampleb[t] = 0.0; g_msumb[t] = 0.0; }
    g_key[t] = 0xFFFFFFFFFFFFFFFFull;
}

// --------------- K1: persistent fp32 SIMT GEMM, 8x8 thread tiles (R8/R13-proven)
// dist rounding = reference: fl(a2+b2) - fl(2*dot), dot fmaf d=0..255 in order.
#define ASTR 132
#define BSTR 132
#define BBUF (16 * BSTR)

__global__ __launch_bounds__(256, 1)
void k1_main(const float* __restrict__ x, const float* __restrict__ cb) {
    extern __shared__ float sm[];              // As[256][132] then Bs[2][16][132]
    __shared__ float a2s[MT];
    __shared__ float b2s[KCB];

    float* As = sm;
    float* Bs = sm + 256 * ASTR;

    const int tid = threadIdx.x;
    const int l   = tid & 31;
    const int tx  = tid & 15;
    const int ty  = tid >> 4;

    for (int i = tid; i < KCB; i += 256) b2s[i] = g_b2[i];

    const int u0 = (int)(((long long)blockIdx.x * NUNITS) / GRIDP);
    const int u1 = (int)(((long long)(blockIdx.x + 1) * NUNITS) / GRIDP);
    int cur_rb = -1;

    const int bcol = tid >> 1;
    const int bdh  = (tid & 1) * 8;

    for (int u = u0; u < u1; u++) {
        const int rb   = u >> 3;
        const int cbk  = u & 7;
        const int row0 = rb * MT;
        const int c0   = cbk * 128;

        if (rb != cur_rb) {
            __syncthreads();                   // prior unit's As readers done
            int arow = tid >> 1, db = (tid & 1) * 128;
            const float4* src = (const float4*)(x + (size_t)(row0 + arow) * DDIM + db);
            #pragma unroll
            for (int q = 0; q < 32; q++) {
                float4 v = src[q];
                int d = db + 4 * q;
                As[(d + 0) * ASTR + arow] = v.x;
                As[(d + 1) * ASTR + arow] = v.y;
                As[(d + 2) * ASTR + arow] = v.z;
                As[(d + 3) * ASTR + arow] = v.w;
            }
            if (tid < MT) {
                const float4* r = (const float4*)(x + (size_t)(row0 + tid) * DDIM);
                double acc = 0.0;
                #pragma unroll 4
                for (int i = 0; i < DDIM / 4; i++) {
                    float4 v = r[i];
                    acc += (double)v.x * v.x + (double)v.y * v.y
                         + (double)v.z * v.z + (double)v.w * v.w;
                }
                a2s[tid] = (float)acc;         // visible after phase-0 sync
            }
            cur_rb = rb;
        }

        float4 rbv0, rbv1;
        auto load_rb = [&](int kc) {
            const float4* src = (const float4*)(cb + (size_t)(c0 + bcol) * DDIM + kc * 16 + bdh);
            rbv0 = src[0]; rbv1 = src[1];
        };
        auto sts_rb = [&](int kc) {
            float* dst = Bs + (kc & 1) * BBUF + bdh * BSTR + bcol;
            dst[0 * BSTR] = rbv0.x; dst[1 * BSTR] = rbv0.y;
            dst[2 * BSTR] = rbv0.z; dst[3 * BSTR] = rbv0.w;
            dst[4 * BSTR] = rbv1.x; dst[5 * BSTR] = rbv1.y;
            dst[6 * BSTR] = rbv1.z; dst[7 * BSTR] = rbv1.w;
        };
        load_rb(0);
        sts_rb(0);

        float a2r[8];
        float acc[8][8];
        #pragma unroll
        for (int i = 0; i < 8; i++)
            #pragma unroll
            for (int j = 0; j < 8; j++) acc[i][j] = 0.0f;

        for (int kc = 0; kc < 16; kc++) {
            if (kc + 1 < 16) load_rb(kc + 1);
            __syncthreads();
            if (kc == 0) {
                #pragma unroll
                for (int i = 0; i < 8; i++) a2r[i] = a2s[ty * 8 + i];
            }
            const float* bbase = Bs + (kc & 1) * BBUF;
            #pragma unroll
            for (int dd = 0; dd < 16; dd++) {
                const float* arow = As + (kc * 16 + dd) * ASTR + ty * 8;
                const float* brow = bbase + dd * BSTR + tx * 8;
                float4 av0 = *(const float4*)(arow);
                float4 av1 = *(const float4*)(arow + 4);
                float4 bv0 = *(const float4*)(brow);
                float4 bv1 = *(const float4*)(brow + 4);
                float a[8] = {av0.x, av0.y, av0.z, av0.w, av1.x, av1.y, av1.z, av1.w};
                float b[8] = {bv0.x, bv0.y, bv0.z, bv0.w, bv1.x, bv1.y, bv1.z, bv1.w};
                #pragma unroll
                for (int i = 0; i < 8; i++)
                    #pragma unroll
                    for (int j = 0; j < 8; j++)
                        acc[i][j] = fmaf(a[i], b[j], acc[i][j]);
            }
            if (kc + 1 < 16) sts_rb(kc + 1);
        }

        // unit epilogue (R8 form): dist, scratch store, lex argmin merge
        const int cc0 = c0 + tx * 8;
        #pragma unroll
        for (int i = 0; i < 8; i++) {
            int R = ty * 8 + i;
            float a2 = a2r[i];
            float bd = 3.402823466e38f; int bc = 0;
            float dv[8];
            #pragma unroll
            for (int j = 0; j < 8; j++) {
                float t = a2 + b2s[cc0 + j];     // fl(a2 + b2)
                float d = t - 2.0f * acc[i][j];  // fl(t - 2ab)
                dv[j] = d;
                if (d < bd) { bd = d; bc = cc0 + j; }   // cols ascend: first-index ties
            }
            float4* dst = (float4*)(g_dist + (size_t)(row0 + R) * KCB + cc0);
            dst[0] = make_float4(dv[0], dv[1], dv[2], dv[3]);
            dst[1] = make_float4(dv[4], dv[5], dv[6], dv[7]);
            #pragma unroll
            for (int off = 8; off >= 1; off >>= 1) {    // lex (d, col) over 16 tx lanes
                float od = __shfl_xor_sync(0xffffffffu, bd, off);
                int   oc = __shfl_xor_sync(0xffffffffu, bc, off);
                if (od < bd || (od == bd && oc < bc)) { bd = od; bc = oc; }
            }
            if ((l & 15) == 0) {
                unsigned long long key =
                    ((unsigned long long)__float_as_uint(bd) << 32) | (unsigned)bc;
                atomicMin(&g_key[row0 + R], key);       // dists > 0: bit-order = value-order
            }
        }
    }
}

// ---- K2 (combined): blocks [0,ENTB) entropy; [ENTB,+OUTB) outputs. Banked atomics.
__global__ __launch_bounds__(256)
void k2_combined(const float* __restrict__ x, const float* __restrict__ cb,
                 float* __restrict__ out, int write_aux) {
    const int tid  = threadIdx.x;
    const int lane = tid & 31;

    if (blockIdx.x < ENTB) {
        // ---------------- entropy: warp/row filtered softmax (proven R2/7/8/13) --
        int row = (blockIdx.x * 256 + tid) >> 5;
        const float4* dr = (const float4*)(g_dist + (size_t)row * KCB);

        float dmin = __uint_as_float((unsigned)(g_key[row] >> 32));
        float thr  = dmin + 0.90f;
        float M    = (-dmin) / 0.01f;

        float4 v[8];
        #pragma unroll
        for (int i = 0; i < 8; i++) v[i] = dr[i * 32 + lane];

        float S = 0.0f;
        #pragma unroll
        for (int i = 0; i < 8; i++) {
            if (v[i].x <= thr) S += expf((-v[i].x) / 0.01f - M);
            if (v[i].y <= thr) S += expf((-v[i].y) / 0.01f - M);
            if (v[i].z <= thr) S += expf((-v[i].z) / 0.01f - M);
            if (v[i].w <= thr) S += expf((-v[i].w) / 0.01f - M);
        }
        #pragma unroll
        for (int off = 16; off >= 1; off >>= 1)
            S += __shfl_xor_sync(0xffffffffu, S, off);

        float logS = logf(S);
        float accent = 0.0f;
        #pragma unroll
        for (int i = 0; i < 8; i++) {
            #pragma unroll
            for (int c = 0; c < 4; c++) {
                float d = (c == 0) ? v[i].x : (c == 1) ? v[i].y : (c == 2) ? v[i].z : v[i].w;
                if (d <= thr) {
                    float sh = (-d) / 0.01f - M;
                    float p  = expf(sh) / S;
                    accent += p * (sh - logS);   // +1e-5 on logits is an fp32 no-op here
                    atomicAdd(&g_avgp[i * 128 + lane * 4 + c], p);
                }
            }
        }
        #pragma unroll
        for (int off = 16; off >= 1; off >>= 1)
            accent += __shfl_xor_sync(0xffffffffu, accent, off);
        if (lane == 0)
            atomicAdd(&g_sampleb[blockIdx.x & (NBANK - 1)], (double)accent);
    } else {
        // ---------------- outputs: 16 rows/CTA, 16 threads/row, MLP-heavy ------
        __shared__ double sred[8];
        const int base   = (blockIdx.x - ENTB) * 16;
        const int r16    = tid >> 4;            // row within CTA
        const int lane16 = tid & 15;
        const int row    = base + r16;

        const int idx = (int)(g_key[row] & 0xFFFFFFFFull);   // broadcast load

        const float4* xr   = (const float4*)(x  + (size_t)row * DDIM);
        const float4* cr   = (const float4*)(cb + (size_t)idx * DDIM);
        float4*       orow = (float4*)(out + (size_t)row * DDIM);

        float4 xv[4], cv[4];
        #pragma unroll
        for (int q = 0; q < 4; q++) {           // 8 independent loads in flight
            int e = q * 16 + lane16;
            xv[q] = xr[e];
            cv[q] = cr[e];
        }
        double lsq = 0.0;
        #pragma unroll
        for (int q = 0; q < 4; q++) {
            int e = q * 16 + lane16;
            float dx = cv[q].x - xv[q].x, dy = cv[q].y - xv[q].y;
            float dz = cv[q].z - xv[q].z, dw = cv[q].w - xv[q].w;
            orow[e] = make_float4(xv[q].x + dx, xv[q].y + dy,
                                  xv[q].z + dz, xv[q].w + dw);
            lsq += (double)dx * dx + (double)dy * dy
                 + (double)dz * dz + (double)dw * dw;
        }
        if (write_aux && lane16 == 0)
            out[(size_t)NROWS * DDIM + 1 + row] = (float)idx;

        #pragma unroll
        for (int off = 16; off >= 1; off >>= 1)
            lsq += __shfl_xor_sync(0xffffffffu, lsq, off);
        if (lane == 0) sred[tid >> 5] = lsq;
        __syncthreads();
        if (tid == 0) {
            double s = 0.0;
            for (int i = 0; i < 8; i++) s += sred[i];
            atomicAdd(&g_msumb[blockIdx.x & (NBANK - 1)], s);
        }
    }
}

// ---------------------------------------------------------------- K3: final loss
__global__ void k3_final(float* out, int write_loss) {
    __shared__ float  w[32];
    __shared__ double banks[2];
    int t    = threadIdx.x;   // 1024 threads
    int lane = t & 31;

    // warp 0 reduces sample banks, warp 1 reduces msum banks (deterministic tree)
    if (t < 32) {
        double s = g_sampleb[t] + g_sampleb[t + 32];
        #pragma unroll
        for (int off = 16; off >= 1; off >>= 1)
            s += __shfl_xor_sync(0xffffffffu, s, off);
        if (t == 0) banks[0] = s;
    } else if (t < 64) {
        double s = g_msumb[lane] + g_msumb[lane + 32];
        #pragma unroll
        for (int off = 16; off >= 1; off >>= 1)
            s += __shfl_xor_sync(0xffffffffu, s, off);
        if (lane == 0) banks[1] = s;
    }

    float ap   = g_avgp[t] / 32768.0f;
    float term = ap * logf(ap + 1e-5f);
    #pragma unroll
    for (int off = 16; off >= 1; off >>= 1)
        term += __shfl_xor_sync(0xffffffffu, term, off);
    if (lane == 0) w[t >> 5] = term;
    __syncthreads();
    if (t == 0) {
        float tot = 0.0f;
        for (int i = 0; i < 32; i++) tot += w[i];
        float avg_ent = -tot;
        float samp    = -(float)(banks[0] / 32768.0);
        float entropy = samp - avg_ent;
        float m       = (float)(banks[1] / 8388608.0);
        float loss    = (m * 0.25f + m) + entropy * 0.1f;
        if (write_loss) out[(size_t)NROWS * DDIM] = loss;
    }
}

// ---------------------------------------------------------------- launch
extern "C" void kernel_launch(void* const* d_in, const int* in_sizes, int n_in,
                              void* d_out, int out_size) {
    const float* x  = (const float*)d_in[0];
    const float* cb = (const float*)d_in[1];
    if (n_in >= 2 && in_sizes[0] == KCB * DDIM && in_sizes[1] == NROWS * DDIM) {
        const float* tmp = x; x = cb; cb = tmp;   // defensive: (codebook, x) order
    }
    float* out = (float*)d_out;
    int aux = (out_size >= NROWS * DDIM + 1 + NROWS) ? 1 : 0;

    static int init_done = 0;
    const int k1_smem = (256 * ASTR + 2 * 16 * BSTR) * 4;   // 152064 bytes
    if (!init_done) {
        cudaFuncSetAttribute(k1_main, cudaFuncAttributeMaxDynamicSharedMemorySize, k1_smem);
        init_done = 1;
    }

    k0_init<<<NROWS / 256, 256>>>(cb);
    k1_main<<<GRIDP, 256, k1_smem>>>(x, cb);
    k2_combined<<<ENTB + OUTB, 256>>>(x, cb, out, aux);
    k3_final<<<1, 1024>>>(out, (out_size > NROWS * DDIM) ? 1 : 0);
}